// round 4
// baseline (speedup 1.0000x reference)
#include <cuda_runtime.h>
#include <math.h>

#define NN      50000
#define NE      800000
#define NHEADS  4
#define NHID    64
#define NHC     256

// ---------------- scratch (static device globals; no allocation) ----------------
__device__ __align__(16) float g_XL[(size_t)NN * NHC];    // 51.2 MB
__device__ __align__(16) float g_XR[(size_t)NN * NHC];    // 51.2 MB
__device__ __align__(16) float g_P [(size_t)NE * NHEADS]; // 12.8 MB exp(logit)
__device__ __align__(16) float g_DEN[(size_t)NN * NHEADS];// 0.8 MB  denom -> 0.25/(d+eps)
__device__ __align__(16) float g_ACC[(size_t)NN * NHID];  // 12.8 MB aggregated messages
__device__ __align__(16) float g_A  [(size_t)NN * NHID];  // 12.8 MB layer input
__device__ __align__(16) int   g_SRC[NE];                 // canonical int32 indices
__device__ __align__(16) int   g_DST[NE];

// ---------------- canonicalize edge_index (handles int32 OR int64 input) -------
// If the buffer holds int64 little-endian indices (all < 2^31, >= 0), every odd
// 32-bit word is 0. If it holds int32 indices, odd words are real indices and
// are nonzero with overwhelming probability within the first 32 pairs.
__global__ void k_convert(const void* __restrict__ ei_raw) {
    __shared__ int s_is64;
    const int* ei32 = (const int*)ei_raw;
    if (threadIdx.x == 0) {
        int nz = 0;
#pragma unroll
        for (int i = 0; i < 32; i++) nz |= ei32[2 * i + 1];
        s_is64 = (nz == 0);
    }
    __syncthreads();
    int e = blockIdx.x * 256 + threadIdx.x;   // grid covers exactly NE
    if (s_is64) {
        const long long* ei64 = (const long long*)ei_raw;
        g_SRC[e] = (int)ei64[e];
        g_DST[e] = (int)ei64[NE + e];
    } else {
        g_SRC[e] = ei32[e];
        g_DST[e] = ei32[NE + e];
    }
}

// ---------------- zero denominators + accumulators ----------------
__global__ void k_zero() {
    int i = blockIdx.x * 256 + threadIdx.x;   // grid covers exactly NN*NHID
    g_ACC[i] = 0.f;
    if (i < NN * NHEADS) g_DEN[i] = 0.f;
}

// ---------------- dual GEMM: O = A[M,K] @ W[K,256] + b ----------------
// blockIdx.z = 0 -> (W1,b1)->g_XL ; 1 -> (W2,b2)->g_XR
// BM=128, BN=128, BK=16, 256 threads, 8x8 micro-tile
template <int K>
__global__ __launch_bounds__(256) void k_gemm(
    const float* __restrict__ Aext, int useA,
    const float* __restrict__ W1, const float* __restrict__ b1,
    const float* __restrict__ W2, const float* __restrict__ b2)
{
    const float* A = useA ? g_A : Aext;
    const float* W = blockIdx.z ? W2 : W1;
    const float* b = blockIdx.z ? b2 : b1;
    float*       O = blockIdx.z ? g_XR : g_XL;

    const int m0 = blockIdx.y * 128;
    const int n0 = blockIdx.x * 128;

    __shared__ __align__(16) float sA[128][20];   // [m][k], padded rows (80B)
    __shared__ __align__(16) float sW[16][132];   // [k][n], padded rows (528B)

    const int tid = threadIdx.x;
    const int ty = tid >> 4, tx = tid & 15;

    float acc[8][8];
#pragma unroll
    for (int i = 0; i < 8; i++)
#pragma unroll
        for (int j = 0; j < 8; j++) acc[i][j] = 0.f;

    for (int kt = 0; kt < K; kt += 16) {
        // load A tile 128x16 (two float4 per thread)
#pragma unroll
        for (int u = 0; u < 2; u++) {
            int slot = tid + u * 256;
            int row = slot >> 2, ch = slot & 3;
            int gr = m0 + row;
            float4 v = make_float4(0.f, 0.f, 0.f, 0.f);
            if (gr < NN) v = *(const float4*)(A + (size_t)gr * K + kt + ch * 4);
            *(float4*)&sA[row][ch * 4] = v;
        }
        // load W tile 16x128 (two float4 per thread)
#pragma unroll
        for (int u = 0; u < 2; u++) {
            int slot = tid + u * 256;
            int kk = slot >> 5, nc = (slot & 31) * 4;
            float4 v = *(const float4*)(W + (size_t)(kt + kk) * NHC + n0 + nc);
            *(float4*)&sW[kk][nc] = v;
        }
        __syncthreads();

#pragma unroll
        for (int kk = 0; kk < 16; kk++) {
            float a[8];
#pragma unroll
            for (int i = 0; i < 8; i++) a[i] = sA[ty * 8 + i][kk];
            float4 w0 = *(float4*)&sW[kk][tx * 8];
            float4 w1 = *(float4*)&sW[kk][tx * 8 + 4];
            float w[8] = {w0.x, w0.y, w0.z, w0.w, w1.x, w1.y, w1.z, w1.w};
#pragma unroll
            for (int i = 0; i < 8; i++)
#pragma unroll
                for (int j = 0; j < 8; j++)
                    acc[i][j] = fmaf(a[i], w[j], acc[i][j]);
        }
        __syncthreads();
    }

    float4 bv0 = *(const float4*)(b + n0 + tx * 8);
    float4 bv1 = *(const float4*)(b + n0 + tx * 8 + 4);
#pragma unroll
    for (int i = 0; i < 8; i++) {
        int gr = m0 + ty * 8 + i;
        if (gr < NN) {
            float4 o0 = make_float4(acc[i][0] + bv0.x, acc[i][1] + bv0.y,
                                    acc[i][2] + bv0.z, acc[i][3] + bv0.w);
            float4 o1 = make_float4(acc[i][4] + bv1.x, acc[i][5] + bv1.y,
                                    acc[i][6] + bv1.z, acc[i][7] + bv1.w);
            float* op = O + (size_t)gr * NHC + n0 + tx * 8;
            *(float4*)op = o0;
            *(float4*)(op + 4) = o1;
        }
    }
}

// ---------------- edge pass A: logits -> p=exp(logit), denom accumulation ------
// 256 threads = 256 hc channels; 4 edges per block-iteration; grid-stride.
__global__ __launch_bounds__(256) void k_edge_a(
    const float* __restrict__ ea,
    const float* __restrict__ We, const float* __restrict__ att)
{
    const int tid = threadIdx.x;
    float wr[9];
#pragma unroll
    for (int k = 0; k < 9; k++) wr[k] = We[k * NHC + tid];
    const float ar = att[tid];

    __shared__ float sea[4][9];
    __shared__ float sred[8][4];

    const int lane = tid & 31, wid = tid >> 5;

    for (int ebase = blockIdx.x * 4; ebase < NE; ebase += gridDim.x * 4) {
        __syncthreads();  // protect sea / sred reuse across iterations
        if (tid < 36) sea[tid / 9][tid % 9] = ea[(size_t)(ebase + tid / 9) * 9 + tid % 9];

        int srcs[4], dsts[4];
#pragma unroll
        for (int s = 0; s < 4; s++) {
            srcs[s] = g_SRC[ebase + s];
            dsts[s] = g_DST[ebase + s];
        }
        float xls[4], xrs[4];
#pragma unroll
        for (int s = 0; s < 4; s++) xls[s] = g_XL[(size_t)srcs[s] * NHC + tid];
#pragma unroll
        for (int s = 0; s < 4; s++) xrs[s] = g_XR[(size_t)dsts[s] * NHC + tid];
        __syncthreads();  // sea ready

        float part[4];
#pragma unroll
        for (int s = 0; s < 4; s++) {
            float ev = 0.f;
#pragma unroll
            for (int k = 0; k < 9; k++) ev = fmaf(wr[k], sea[s][k], ev);
            float m = xls[s] + xrs[s] + ev;
            float sv = (m > 0.f) ? m : 0.2f * m;   // leaky_relu slope 0.2
            part[s] = sv * ar;
        }
#pragma unroll
        for (int s = 0; s < 4; s++) {
#pragma unroll
            for (int off = 16; off > 0; off >>= 1)
                part[s] += __shfl_down_sync(0xffffffffu, part[s], off);
        }
        if (lane == 0) {
#pragma unroll
            for (int s = 0; s < 4; s++) sred[wid][s] = part[s];
        }
        __syncthreads();
        if (tid < 16) {
            int h = tid >> 2, s = tid & 3;
            float logit = sred[2 * h][s] + sred[2 * h + 1][s];
            float p = expf(logit);
            g_P[(size_t)(ebase + s) * 4 + h] = p;
            atomicAdd(&g_DEN[(size_t)dsts[s] * 4 + h], p);
        }
    }
}

// ---------------- invert denominators (fold 1/H head-mean in) ----------------
__global__ void k_invden() {
    int i = blockIdx.x * 256 + threadIdx.x;
    if (i < NN * NHEADS) g_DEN[i] = 0.25f / (g_DEN[i] + 1e-16f);
}

// ---------------- edge pass B: scatter messages (head-mean folded) ----------------
// 16 threads per edge, 16 edges per 256-thread block.
__global__ __launch_bounds__(256) void k_edge_b() {
    const int tid = threadIdx.x;
    const int slot = tid >> 4, q = tid & 15;
    const int e = blockIdx.x * 16 + slot;
    const int src = g_SRC[e];
    const int dst = g_DST[e];

    float al[4];
#pragma unroll
    for (int h = 0; h < 4; h++)
        al[h] = g_P[(size_t)e * 4 + h] * g_DEN[(size_t)dst * 4 + h];

    float4 acc = make_float4(0.f, 0.f, 0.f, 0.f);
    const float* base = g_XL + (size_t)src * NHC + q * 4;
#pragma unroll
    for (int h = 0; h < 4; h++) {
        float4 v = *(const float4*)(base + h * 64);
        acc.x = fmaf(v.x, al[h], acc.x);
        acc.y = fmaf(v.y, al[h], acc.y);
        acc.z = fmaf(v.z, al[h], acc.z);
        acc.w = fmaf(v.w, al[h], acc.w);
    }
    atomicAdd((float4*)(g_ACC + (size_t)dst * 64 + q * 4), acc);
}

// ---------------- node update: bias, gating, leaky-relu ----------------
__global__ void k_node(const float* __restrict__ bias, const float* __restrict__ gates,
                       int layer, float* __restrict__ out) {
    int i = blockIdx.x * 256 + threadIdx.x;   // grid covers exactly NN*NHID
    int c = i & 63;
    float val = g_ACC[i] + bias[c];
    if (layer == 0) {
        g_A[i] = (val > 0.f) ? val : 0.01f * val;
    } else {
        float g = 1.f / (1.f + expf(-gates[layer - 1]));
        float h = g * val + (1.f - g) * g_A[i];
        if (layer == 1) g_A[i] = (h > 0.f) ? h : 0.01f * h;
        else            out[i] = h;
    }
}

// ---------------- host ----------------
extern "C" void kernel_launch(void* const* d_in, const int* in_sizes, int n_in,
                              void* d_out, int out_size) {
    (void)out_size;
    // identify inputs by element count + appearance order (identical relative
    // order under both dict ordering and signature ordering)
    const float *x = 0, *edge_attr = 0, *gates = 0;
    const float *W32k[4] = {0, 0, 0, 0};  int n32k = 0;   // init_Wl, init_Wr, Wl, Wr
    const float *a256[3] = {0, 0, 0};     int n256 = 0;   // init_bl, init_br, init_att
    const float *a512[3] = {0, 0, 0};     int n512 = 0;   // bl, br, att
    const float *init_We = 0, *WeL = 0, *init_bias = 0, *biasL = 0;
    const void* ei = 0;

    for (int i = 0; i < n_in; i++) {
        const void* p = d_in[i];
        switch (in_sizes[i]) {
            case 6400000: x = (const float*)p; break;
            case 7200000: edge_attr = (const float*)p; break;
            case 1600000: ei = p; break;
            case 3:       gates = (const float*)p; break;
            case 32768:   if (n32k < 4) W32k[n32k++] = (const float*)p; break;
            case 256:     if (n256 < 3) a256[n256++] = (const float*)p; break;
            case 512:     if (n512 < 3) a512[n512++] = (const float*)p; break;
            case 2304:    init_We = (const float*)p; break;
            case 4608:    WeL = (const float*)p; break;
            case 64:      init_bias = (const float*)p; break;
            case 128:     biasL = (const float*)p; break;
            default: break;
        }
    }
    const float *Wl0 = W32k[0], *Wr0 = W32k[1], *WlL = W32k[2], *WrL = W32k[3];
    const float *bl0 = a256[0], *br0 = a256[1], *att0 = a256[2];
    const float *blL = a512[0], *brL = a512[1], *attL = a512[2];
    float* out = (float*)d_out;

    k_convert<<<NE / 256, 256>>>(ei);

    const dim3 gemm_grid(2, (NN + 127) / 128, 2);

    for (int l = 0; l < 3; l++) {
        k_zero<<<NN * NHID / 256, 256>>>();

        if (l == 0) {
            k_gemm<128><<<gemm_grid, 256>>>(x, 0, Wl0, bl0, Wr0, br0);
        } else {
            const float* Wl = WlL + (size_t)(l - 1) * 64 * 256;
            const float* Wr = WrL + (size_t)(l - 1) * 64 * 256;
            const float* bl = blL + (size_t)(l - 1) * 256;
            const float* br = brL + (size_t)(l - 1) * 256;
            k_gemm<64><<<gemm_grid, 256>>>(0, 1, Wl, bl, Wr, br);
        }

        const float* We  = l ? (WeL  + (size_t)(l - 1) * 9 * 256) : init_We;
        const float* att = l ? (attL + (size_t)(l - 1) * 256)     : att0;

        k_edge_a<<<2368, 256>>>(edge_attr, We, att);
        k_invden<<<(NN * NHEADS + 255) / 256, 256>>>();
        k_edge_b<<<NE / 16, 256>>>();

        const float* bias = l ? (biasL + (size_t)(l - 1) * 64) : init_bias;
        k_node<<<NN * NHID / 256, 256>>>(bias, gates, l, out);
    }
}